// round 3
// baseline (speedup 1.0000x reference)
#include <cuda_runtime.h>

#define NPTS    200000
#define NREL    128
#define CAP     4096       // per-relation slot capacity (mean 1562, sd 39)
#define CHUNKS  24         // CTAs per relation in the main kernel
#define WPC     4          // warps per CTA (128 threads)
#define SCT_PTS 2048       // points per scatter block

// ---- device scratch (no allocations allowed) ----
__device__ int g_counts[NREL];
__device__ int g_pids[NREL * CAP];
__device__ int g_ovf_count;
__device__ int g_ovf[NPTS];

// Reset counters (graph replays => must run every launch).
__global__ void k_reset() {
    if (threadIdx.x < NREL) g_counts[threadIdx.x] = 0;
    if (threadIdx.x == 0) g_ovf_count = 0;
}

// Block-aggregated scatter: smem-local binning, ONE global atomic per
// (bin, block) to reserve a range, then conflict-spread smem atomics for
// local positions. Order within a bin is irrelevant (points independent).
__global__ void __launch_bounds__(256)
k_scatter(const int* __restrict__ rel, int n) {
    __shared__ int s_rel[SCT_PTS];
    __shared__ int s_hist[NREL];
    __shared__ int s_base[NREL];

    int start = blockIdx.x * SCT_PTS;
    int cnt = n - start;
    if (cnt > SCT_PTS) cnt = SCT_PTS;
    if (cnt <= 0) return;

    for (int i = threadIdx.x; i < NREL; i += blockDim.x) s_hist[i] = 0;
    __syncthreads();

    for (int i = threadIdx.x; i < cnt; i += blockDim.x) {
        int r = __ldg(rel + start + i);
        s_rel[i] = r;
        atomicAdd(&s_hist[r], 1);
    }
    __syncthreads();

    for (int i = threadIdx.x; i < NREL; i += blockDim.x) {
        int c = s_hist[i];
        s_base[i] = c ? atomicAdd(&g_counts[i], c) : 0;
        s_hist[i] = 0;   // reuse as local cursor
    }
    __syncthreads();

    for (int i = threadIdx.x; i < cnt; i += blockDim.x) {
        int r = s_rel[i];
        int pos = s_base[r] + atomicAdd(&s_hist[r], 1);
        if (pos < CAP) {
            g_pids[r * CAP + pos] = start + i;
        } else {                      // statistically unreachable guard
            int o = atomicAdd(&g_ovf_count, 1);
            g_ovf[o] = start + i;
        }
    }
}

// Main: CTA = (relation r, chunk). lane = 2*b + h owns block b, out-half h;
// its 32 weight floats live in registers for the whole CTA.
//
// Each warp owns a CONTIGUOUS segment of its relation's bin:
//  - 32 consecutive pids fetched with ONE coalesced LDG, broadcast via shfl
//    (pid load is off the critical path; no dependent pid->x chain)
//  - x row for iteration k+1 prefetched while computing/storing iteration k
// Per point: 512B coalesced x read + 512B coalesced out write.
__global__ void __launch_bounds__(32 * WPC)
k_main(const float4* __restrict__ x4,
       const float4* __restrict__ w4,
       const int* __restrict__ rel,
       float4* __restrict__ out4) {
    int r     = blockIdx.x / CHUNKS;
    int chunk = blockIdx.x % CHUNKS;
    int lane  = threadIdx.x & 31;
    int wrp   = threadIdx.x >> 5;
    int b     = lane >> 1;
    int h     = lane & 1;

    const float4* wp = w4 + (size_t)((r * 16 + b) * 8) * 2 + h;
    float4 wt[8];
#pragma unroll
    for (int i = 0; i < 8; i++) wt[i] = __ldg(wp + 2 * i);

    int cnt = g_counts[r];
    if (cnt > CAP) cnt = CAP;
    const int* pids = g_pids + r * CAP;

    const int nw  = CHUNKS * WPC;          // warps per relation (96)
    int wj        = chunk * WPC + wrp;     // warp index within relation
    int seg       = (cnt + nw - 1) / nw;   // contiguous points per warp
    int start     = wj * seg;
    int end       = start + seg;
    if (end > cnt) end = cnt;

    for (int base = start; base < end; base += 32) {
        int m = end - base;
        if (m > 32) m = 32;
        int mypid = (base + lane < end) ? __ldg(pids + base + lane) : 0;

        int p = __shfl_sync(0xffffffffu, mypid, 0);
        float4 xa = __ldg(x4 + (size_t)p * 32 + 2 * b);
        float4 xb = __ldg(x4 + (size_t)p * 32 + 2 * b + 1);

        for (int k = 0; k < m; k++) {
            int p2 = 0;
            float4 xa2 = xa, xb2 = xb;
            if (k + 1 < m) {
                p2  = __shfl_sync(0xffffffffu, mypid, k + 1);
                xa2 = __ldg(x4 + (size_t)p2 * 32 + 2 * b);
                xb2 = __ldg(x4 + (size_t)p2 * 32 + 2 * b + 1);
            }

            float xs[8] = {xa.x, xa.y, xa.z, xa.w, xb.x, xb.y, xb.z, xb.w};
            float a0 = 0.f, a1 = 0.f, a2 = 0.f, a3 = 0.f;
#pragma unroll
            for (int i = 0; i < 8; i++) {
                a0 = fmaf(xs[i], wt[i].x, a0);
                a1 = fmaf(xs[i], wt[i].y, a1);
                a2 = fmaf(xs[i], wt[i].z, a2);
                a3 = fmaf(xs[i], wt[i].w, a3);
            }
            out4[(size_t)p * 32 + lane] = make_float4(a0, a1, a2, a3);

            p = p2; xa = xa2; xb = xb2;
        }
    }

    // Overflow epilogue (statistically unreachable; g_ovf_count == 0 in
    // practice, costing one uniform load + exit). Direct weight gather.
    int total = g_ovf_count;
    if (total > 0) {
        int wg      = blockIdx.x * WPC + wrp;
        int nwarps  = NREL * CHUNKS * WPC;
        for (int idx = wg; idx < total; idx += nwarps) {
            int p  = g_ovf[idx];
            int r2 = __ldg(rel + p);
            const float4* wq = w4 + (size_t)((r2 * 16 + b) * 8) * 2 + h;
            float4 xa = __ldg(x4 + (size_t)p * 32 + 2 * b);
            float4 xb = __ldg(x4 + (size_t)p * 32 + 2 * b + 1);
            float xs[8] = {xa.x, xa.y, xa.z, xa.w, xb.x, xb.y, xb.z, xb.w};
            float a0 = 0.f, a1 = 0.f, a2 = 0.f, a3 = 0.f;
#pragma unroll
            for (int i = 0; i < 8; i++) {
                float4 w = __ldg(wq + 2 * i);
                a0 = fmaf(xs[i], w.x, a0);
                a1 = fmaf(xs[i], w.y, a1);
                a2 = fmaf(xs[i], w.z, a2);
                a3 = fmaf(xs[i], w.w, a3);
            }
            out4[(size_t)p * 32 + lane] = make_float4(a0, a1, a2, a3);
        }
    }
}

extern "C" void kernel_launch(void* const* d_in, const int* in_sizes, int n_in,
                              void* d_out, int out_size) {
    const float* x      = (const float*)d_in[0];   // [NPTS, 128] f32
    const float* blocks = (const float*)d_in[1];   // [128,16,8,8] f32
    const int*   rel    = (const int*)d_in[2];     // [NPTS] i32
    int n = in_sizes[2];
    if (n > NPTS) n = NPTS;  // scratch bound

    k_reset<<<1, 128>>>();
    k_scatter<<<(n + SCT_PTS - 1) / SCT_PTS, 256>>>(rel, n);
    k_main<<<NREL * CHUNKS, 32 * WPC>>>(
        (const float4*)x, (const float4*)blocks, rel, (float4*)d_out);
}